// round 8
// baseline (speedup 1.0000x reference)
#include <cuda_runtime.h>

#define TT   8
#define NS   512
#define NP   64
#define NTOT 32768   // NS*NP

// Scratch for GAT output -> graph LSTM input ([T, N, 32])
__device__ float g_graph_in[(size_t)TT * NTOT * 32];

typedef unsigned long long u64;

__device__ __forceinline__ u64 ffma2(u64 a, u64 b, u64 c) {
    u64 d;
    asm("fma.rn.f32x2 %0, %1, %2, %3;" : "=l"(d) : "l"(a), "l"(b), "l"(c));
    return d;
}
__device__ __forceinline__ u64 pk2(float lo, float hi) {
    u64 r;
    asm("mov.b64 %0, {%1, %2};" : "=l"(r) : "f"(lo), "f"(hi));
    return r;
}
__device__ __forceinline__ float lo2(u64 v) { return __uint_as_float((unsigned)v); }
__device__ __forceinline__ float hi2(u64 v) { return __uint_as_float((unsigned)(v >> 32)); }

__device__ __forceinline__ float sigmf_(float x) {
    return __fdividef(1.f, 1.f + __expf(-x));
}
__device__ __forceinline__ float tanhf_(float x) {
    float e = __expf(-2.f * fabsf(x));
    float r = __fdividef(1.f - e, 1.f + e);
    return copysignf(r, x);
}

// ---------------------------------------------------------------------------
// LSTM: one thread per pedestrian row, h/c in registers, 8 sequential steps.
// D = input feature dim (3 for traj, 32 for graph). ENC: also emit encoded.
// ---------------------------------------------------------------------------
template<int D, bool ENC>
__global__ void __launch_bounds__(128) lstm_kernel(
    const float* __restrict__ xseq,    // [T, N, D]
    const float* __restrict__ h0, const float* __restrict__ c0,   // [N,32]
    const float* __restrict__ Wih,     // [128, D]
    const float* __restrict__ Whh,     // [128, 32]
    const float* __restrict__ bih, const float* __restrict__ bhh, // [128]
    float* __restrict__ hsout,         // [T, N, 32]
    const float* __restrict__ traj_last, // [N,32] (ENC only)
    const float* __restrict__ znoise,    // [S,8]  (ENC only)
    float* __restrict__ enc)             // [N,72] (ENC only)
{
    __shared__ __align__(16) float sWhh[128 * 32];
    __shared__ __align__(16) float sWih[128 * D];
    __shared__ float sB[128];

    const int tid = threadIdx.x;
    for (int i = tid; i < 128 * 32; i += 128) sWhh[i] = Whh[i];
    for (int i = tid; i < 128 * D;  i += 128) sWih[i] = Wih[i];
    sB[tid] = bih[tid] + bhh[tid];
    __syncthreads();

    const int n = blockIdx.x * 128 + tid;

    float c[32], hn[32];
    u64 h2[16];
    {
        const float4* hv4 = reinterpret_cast<const float4*>(h0 + (size_t)n * 32);
        const float4* cv4 = reinterpret_cast<const float4*>(c0 + (size_t)n * 32);
        #pragma unroll
        for (int j = 0; j < 8; j++) {
            float4 hv = hv4[j]; float4 cv = cv4[j];
            h2[2*j]   = pk2(hv.x, hv.y);
            h2[2*j+1] = pk2(hv.z, hv.w);
            c[4*j] = cv.x; c[4*j+1] = cv.y; c[4*j+2] = cv.z; c[4*j+3] = cv.w;
        }
    }

    #pragma unroll 1
    for (int t = 0; t < TT; t++) {
        float x0 = 0.f, x1 = 0.f, x2 = 0.f;
        u64 xv2[(D == 32) ? 16 : 1];
        if constexpr (D == 3) {
            const float* xp = xseq + ((size_t)t * NTOT + n) * 3;
            x0 = xp[0]; x1 = xp[1]; x2 = xp[2];
        } else {
            const float4* xp4 = reinterpret_cast<const float4*>(xseq + ((size_t)t * NTOT + n) * 32);
            #pragma unroll
            for (int j = 0; j < 8; j++) {
                float4 v = xp4[j];
                xv2[2*j]   = pk2(v.x, v.y);
                xv2[2*j+1] = pk2(v.z, v.w);
            }
        }

        #pragma unroll
        for (int k = 0; k < 32; k++) {
            const u64* wr0 = reinterpret_cast<const u64*>(sWhh + (k      ) * 32);
            const u64* wr1 = reinterpret_cast<const u64*>(sWhh + (k + 32 ) * 32);
            const u64* wr2 = reinterpret_cast<const u64*>(sWhh + (k + 64 ) * 32);
            const u64* wr3 = reinterpret_cast<const u64*>(sWhh + (k + 96 ) * 32);
            u64 a0 = 0, a1 = 0, a2 = 0, a3 = 0;
            #pragma unroll
            for (int j = 0; j < 16; j++) {
                u64 hv = h2[j];
                a0 = ffma2(wr0[j], hv, a0);
                a1 = ffma2(wr1[j], hv, a1);
                a2 = ffma2(wr2[j], hv, a2);
                a3 = ffma2(wr3[j], hv, a3);
            }
            if constexpr (D == 32) {
                const u64* vr0 = reinterpret_cast<const u64*>(sWih + (k      ) * 32);
                const u64* vr1 = reinterpret_cast<const u64*>(sWih + (k + 32 ) * 32);
                const u64* vr2 = reinterpret_cast<const u64*>(sWih + (k + 64 ) * 32);
                const u64* vr3 = reinterpret_cast<const u64*>(sWih + (k + 96 ) * 32);
                #pragma unroll
                for (int j = 0; j < 16; j++) {
                    u64 xv = xv2[j];
                    a0 = ffma2(vr0[j], xv, a0);
                    a1 = ffma2(vr1[j], xv, a1);
                    a2 = ffma2(vr2[j], xv, a2);
                    a3 = ffma2(vr3[j], xv, a3);
                }
            }
            float gi = lo2(a0) + hi2(a0) + sB[k];
            float gf = lo2(a1) + hi2(a1) + sB[32 + k];
            float gg = lo2(a2) + hi2(a2) + sB[64 + k];
            float go = lo2(a3) + hi2(a3) + sB[96 + k];
            if constexpr (D == 3) {
                gi += sWih[(k      )*3]*x0 + sWih[(k      )*3+1]*x1 + sWih[(k      )*3+2]*x2;
                gf += sWih[(k + 32 )*3]*x0 + sWih[(k + 32 )*3+1]*x1 + sWih[(k + 32 )*3+2]*x2;
                gg += sWih[(k + 64 )*3]*x0 + sWih[(k + 64 )*3+1]*x1 + sWih[(k + 64 )*3+2]*x2;
                go += sWih[(k + 96 )*3]*x0 + sWih[(k + 96 )*3+1]*x1 + sWih[(k + 96 )*3+2]*x2;
            }
            float cn = sigmf_(gf) * c[k] + sigmf_(gi) * tanhf_(gg);
            c[k]  = cn;
            hn[k] = sigmf_(go) * tanhf_(cn);
        }

        float* op = hsout + ((size_t)t * NTOT + n) * 32;
        #pragma unroll
        for (int j = 0; j < 8; j++) {
            h2[2*j]   = pk2(hn[4*j],     hn[4*j + 1]);
            h2[2*j+1] = pk2(hn[4*j + 2], hn[4*j + 3]);
            reinterpret_cast<float4*>(op)[j] =
                make_float4(hn[4*j], hn[4*j+1], hn[4*j+2], hn[4*j+3]);
        }

        if (ENC && t == TT - 1) {
            float* ep = enc + (size_t)n * 72;
            const float4* tl = reinterpret_cast<const float4*>(traj_last + (size_t)n * 32);
            #pragma unroll
            for (int j = 0; j < 8; j++) reinterpret_cast<float4*>(ep)[j] = tl[j];
            #pragma unroll
            for (int j = 0; j < 8; j++)
                reinterpret_cast<float4*>(ep + 32)[j] =
                    make_float4(hn[4*j], hn[4*j+1], hn[4*j+2], hn[4*j+3]);
            const float4* zp = reinterpret_cast<const float4*>(znoise + (size_t)(n >> 6) * 8);
            reinterpret_cast<float4*>(ep + 64)[0] = zp[0];
            reinterpret_cast<float4*>(ep + 64)[1] = zp[1];
        }
    }
}

// ---------------------------------------------------------------------------
// GAT encoder: one block per (scene, t). 256 threads. All tiles in shared.
// ---------------------------------------------------------------------------
#define GAT_SMEM_FLOATS 22512
#define GAT_SMEM_BYTES  (GAT_SMEM_FLOATS * 4)

__global__ void __launch_bounds__(256) gat_kernel(
    const float* __restrict__ trajhs,   // [T, N, 32]
    const float* __restrict__ w0,       // [4,32,16]
    const float* __restrict__ asrc0, const float* __restrict__ adst0,  // [4,16]
    const float* __restrict__ bias0,    // [16]
    const float* __restrict__ w1,       // [1,64,32]
    const float* __restrict__ asrc1, const float* __restrict__ adst1,  // [32]
    const float* __restrict__ bias1,    // [32]
    float* __restrict__ gout)           // [T, N, 32]
{
    extern __shared__ __align__(16) float sm[];
    float* XN  = sm;           // 64 x 33
    float* W0S = sm + 2112;    // 32 x 64  (col = h*16+o)
    float* HP0 = sm + 4160;    // 64 x 68
    float* S0  = sm + 8512;    // 4 x 64
    float* D0  = sm + 8768;    // 4 x 64
    float* X1  = sm + 9024;    // 64 x 68  (feat = h*16+o)
    float* W1S = sm + 13376;   // 64 x 32
    float* HP1 = sm + 15424;   // 64 x 36
    float* S1  = sm + 17728;   // 64
    float* D1  = sm + 17792;   // 64
    float* EM  = sm + 17856;   // 64 x 68
    float* ES  = sm + 22208;   // 64
    float* A0S = sm + 22272;   // 64
    float* A0D = sm + 22336;   // 64
    float* A1S = sm + 22400;   // 32
    float* A1D = sm + 22432;   // 32
    float* B0  = sm + 22464;   // 16
    float* B1  = sm + 22480;   // 32

    const int tid = threadIdx.x;
    const int b = blockIdx.x;
    const int s = b >> 3, t = b & 7;

    const float* src = trajhs + ((size_t)t * NTOT + s * 64) * 32;
    for (int i = tid; i < 2048; i += 256) XN[(i >> 5) * 33 + (i & 31)] = src[i];
    for (int i = tid; i < 2048; i += 256) {
        int f = i >> 6, cc = i & 63;
        W0S[i] = w0[((cc >> 4) << 9) + (f << 4) + (cc & 15)];
    }
    for (int i = tid; i < 2048; i += 256) W1S[i] = w1[i];
    if (tid < 64)       { A0S[tid] = asrc0[tid]; A0D[tid] = adst0[tid]; }
    else if (tid < 96)  { A1S[tid - 64] = asrc1[tid - 64]; A1D[tid - 64] = adst1[tid - 64]; }
    else if (tid < 112) { B0[tid - 96] = bias0[tid - 96]; }
    else if (tid < 144) { B1[tid - 112] = bias1[tid - 112]; }
    __syncthreads();

    // --- instance norm over 64 peds, 32 features ---
    if (tid < 32) {
        const int f = tid;
        float m = 0.f;
        #pragma unroll 8
        for (int p = 0; p < 64; p++) m += XN[p * 33 + f];
        m *= 0.015625f;
        float v = 0.f;
        #pragma unroll 8
        for (int p = 0; p < 64; p++) { float d = XN[p * 33 + f] - m; v = fmaf(d, d, v); }
        float inv = rsqrtf(fmaf(v, 0.015625f, 1e-5f));
        #pragma unroll 8
        for (int p = 0; p < 64; p++) XN[p * 33 + f] = (XN[p * 33 + f] - m) * inv;
    }
    __syncthreads();

    // --- hp0 = xn @ w0 : [64x32] @ [32x64] ---
    {
        const int p  = tid >> 2;
        const int cb = (tid & 3) << 4;
        u64 acc[8] = {0, 0, 0, 0, 0, 0, 0, 0};
        #pragma unroll
        for (int f = 0; f < 32; f++) {
            float xv = XN[p * 33 + f];
            u64 xx = pk2(xv, xv);
            const u64* w = reinterpret_cast<const u64*>(W0S + f * 64 + cb);
            #pragma unroll
            for (int j = 0; j < 8; j++) acc[j] = ffma2(w[j], xx, acc[j]);
        }
        u64* dst = reinterpret_cast<u64*>(HP0 + p * 68 + cb);
        #pragma unroll
        for (int j = 0; j < 8; j++) dst[j] = acc[j];
    }
    __syncthreads();

    // --- s0, d0 ---
    {
        const int h = tid >> 6, p = tid & 63;
        const float* hb = HP0 + p * 68 + h * 16;
        const float* as = A0S + h * 16;
        const float* ad = A0D + h * 16;
        float sv = 0.f, dv = 0.f;
        #pragma unroll
        for (int o = 0; o < 16; o++) {
            float hv = hb[o];
            sv = fmaf(hv, as[o], sv);
            dv = fmaf(hv, ad[o], dv);
        }
        S0[h * 64 + p] = sv;
        D0[h * 64 + p] = dv;
    }
    __syncthreads();

    // --- attention0: softmax over q, apply to hp0, +bias, elu -> X1 ---
    {
        const int h = tid >> 6, p = tid & 63;
        const float sp = S0[h * 64 + p];
        const float* dd = D0 + h * 64;
        float mx = -3.4e38f;
        #pragma unroll 8
        for (int q = 0; q < 64; q++) {
            float e = sp + dd[q];
            e = e > 0.f ? e : 0.2f * e;
            mx = fmaxf(mx, e);
        }
        u64 acc[8] = {0, 0, 0, 0, 0, 0, 0, 0};
        float den = 0.f;
        #pragma unroll 2
        for (int q = 0; q < 64; q++) {
            float e = sp + dd[q];
            e = e > 0.f ? e : 0.2f * e;
            float w = __expf(e - mx);
            den += w;
            u64 ww = pk2(w, w);
            const u64* hq = reinterpret_cast<const u64*>(HP0 + q * 68 + h * 16);
            #pragma unroll
            for (int j = 0; j < 8; j++) acc[j] = ffma2(hq[j], ww, acc[j]);
        }
        float inv = __fdividef(1.f, den);
        float* xo = X1 + p * 68 + h * 16;
        #pragma unroll
        for (int j = 0; j < 8; j++) {
            float v0 = fmaf(lo2(acc[j]), inv, B0[2 * j]);
            float v1 = fmaf(hi2(acc[j]), inv, B0[2 * j + 1]);
            v0 = v0 > 0.f ? v0 : expm1f(v0);
            v1 = v1 > 0.f ? v1 : expm1f(v1);
            xo[2 * j] = v0;
            xo[2 * j + 1] = v1;
        }
    }
    __syncthreads();

    // --- instance norm over 64 peds, 64 features ---
    if (tid < 64) {
        const int f = tid;
        float m = 0.f;
        #pragma unroll 8
        for (int p = 0; p < 64; p++) m += X1[p * 68 + f];
        m *= 0.015625f;
        float v = 0.f;
        #pragma unroll 8
        for (int p = 0; p < 64; p++) { float d = X1[p * 68 + f] - m; v = fmaf(d, d, v); }
        float inv = rsqrtf(fmaf(v, 0.015625f, 1e-5f));
        #pragma unroll 8
        for (int p = 0; p < 64; p++) X1[p * 68 + f] = (X1[p * 68 + f] - m) * inv;
    }
    __syncthreads();

    // --- hp1 = x1 @ w1 : [64x64] @ [64x32] ---
    {
        const int p  = tid >> 2;
        const int ob = (tid & 3) << 3;
        u64 acc[4] = {0, 0, 0, 0};
        #pragma unroll
        for (int f = 0; f < 64; f++) {
            float xv = X1[p * 68 + f];
            u64 xx = pk2(xv, xv);
            const u64* w = reinterpret_cast<const u64*>(W1S + f * 32 + ob);
            #pragma unroll
            for (int j = 0; j < 4; j++) acc[j] = ffma2(w[j], xx, acc[j]);
        }
        u64* dst = reinterpret_cast<u64*>(HP1 + p * 36 + ob);
        #pragma unroll
        for (int j = 0; j < 4; j++) dst[j] = acc[j];
    }
    __syncthreads();

    // --- s1, d1 ---
    if (tid < 64) {
        const float* hb = HP1 + tid * 36;
        float sv = 0.f, dv = 0.f;
        #pragma unroll
        for (int o = 0; o < 32; o++) {
            float hv = hb[o];
            sv = fmaf(hv, A1S[o], sv);
            dv = fmaf(hv, A1D[o], dv);
        }
        S1[tid] = sv;
        D1[tid] = dv;
    }
    __syncthreads();

    // --- softmax weights for layer 1 ---
    if (tid < 64) {
        const int p = tid;
        const float sp = S1[p];
        float mx = -3.4e38f;
        #pragma unroll 8
        for (int q = 0; q < 64; q++) {
            float e = sp + D1[q];
            e = e > 0.f ? e : 0.2f * e;
            mx = fmaxf(mx, e);
        }
        float den = 0.f;
        #pragma unroll 2
        for (int q = 0; q < 64; q++) {
            float e = sp + D1[q];
            e = e > 0.f ? e : 0.2f * e;
            float w = __expf(e - mx);
            EM[p * 68 + q] = w;
            den += w;
        }
        ES[p] = __fdividef(1.f, den);
    }
    __syncthreads();

    // --- apply attn1, +bias, write graph_in ---
    {
        const int p  = tid >> 2;
        const int ob = (tid & 3) << 3;
        u64 acc[4] = {0, 0, 0, 0};
        const float* ew = EM + p * 68;
        #pragma unroll 2
        for (int q = 0; q < 64; q++) {
            float w = ew[q];
            u64 ww = pk2(w, w);
            const u64* hq = reinterpret_cast<const u64*>(HP1 + q * 36 + ob);
            #pragma unroll
            for (int j = 0; j < 4; j++) acc[j] = ffma2(hq[j], ww, acc[j]);
        }
        float inv = ES[p];
        float2* gp = reinterpret_cast<float2*>(
            gout + ((size_t)t * NTOT + s * 64 + p) * 32 + ob);
        #pragma unroll
        for (int j = 0; j < 4; j++) {
            float v0 = fmaf(lo2(acc[j]), inv, B1[ob + 2 * j]);
            float v1 = fmaf(hi2(acc[j]), inv, B1[ob + 2 * j + 1]);
            gp[j] = make_float2(v0, v1);
        }
    }
}

// ---------------------------------------------------------------------------
extern "C" void kernel_launch(void* const* d_in, const int* in_sizes, int n_in,
                              void* d_out, int out_size)
{
    (void)in_sizes; (void)n_in; (void)out_size;
    const float* obs  = (const float*)d_in[0];
    const float* h0t  = (const float*)d_in[1];
    const float* c0t  = (const float*)d_in[2];
    const float* h0g  = (const float*)d_in[3];
    const float* c0g  = (const float*)d_in[4];
    const float* zn   = (const float*)d_in[5];
    const float* WihT = (const float*)d_in[6];
    const float* WhhT = (const float*)d_in[7];
    const float* bihT = (const float*)d_in[8];
    const float* bhhT = (const float*)d_in[9];
    const float* WihG = (const float*)d_in[10];
    const float* WhhG = (const float*)d_in[11];
    const float* bihG = (const float*)d_in[12];
    const float* bhhG = (const float*)d_in[13];
    const float* w0   = (const float*)d_in[14];
    const float* as0  = (const float*)d_in[15];
    const float* ad0  = (const float*)d_in[16];
    const float* b0   = (const float*)d_in[17];
    const float* w1   = (const float*)d_in[18];
    const float* as1  = (const float*)d_in[19];
    const float* ad1  = (const float*)d_in[20];
    const float* b1   = (const float*)d_in[21];

    float* out = (float*)d_out;
    float* enc = out;                                  // [N,72]
    float* ghs = out + (size_t)NTOT * 72;              // [T,N,32]
    float* ths = ghs + (size_t)TT * NTOT * 32;         // [T,N,32]

    float* gin = nullptr;
    cudaGetSymbolAddress((void**)&gin, g_graph_in);

    // 1) traj LSTM -> traj_hs (directly into output region)
    lstm_kernel<3, false><<<NTOT / 128, 128>>>(
        obs, h0t, c0t, WihT, WhhT, bihT, bhhT, ths, nullptr, nullptr, nullptr);

    // 2) GAT encoder -> graph_in scratch
    cudaFuncSetAttribute(gat_kernel,
                         cudaFuncAttributeMaxDynamicSharedMemorySize, GAT_SMEM_BYTES);
    gat_kernel<<<NS * TT, 256, GAT_SMEM_BYTES>>>(
        ths, w0, as0, ad0, b0, w1, as1, ad1, b1, gin);

    // 3) graph LSTM -> graph_hs + encoded (traj_hs[-1] | graph_hs[-1] | noise)
    lstm_kernel<32, true><<<NTOT / 128, 128>>>(
        gin, h0g, c0g, WihG, WhhG, bihG, bhhG, ghs,
        ths + (size_t)(TT - 1) * NTOT * 32, zn, enc);
}

// round 9
// speedup vs baseline: 2.0154x; 2.0154x over previous
#include <cuda_runtime.h>

#define TT   8
#define NS   512
#define NP   64
#define NTOT 32768   // NS*NP

// Scratch for GAT output -> graph LSTM input ([T, N, 32])
__device__ float g_graph_in[(size_t)TT * NTOT * 32];

typedef unsigned long long u64;

__device__ __forceinline__ u64 ffma2(u64 a, u64 b, u64 c) {
    u64 d;
    asm("fma.rn.f32x2 %0, %1, %2, %3;" : "=l"(d) : "l"(a), "l"(b), "l"(c));
    return d;
}
__device__ __forceinline__ u64 pk2(float lo, float hi) {
    u64 r;
    asm("mov.b64 %0, {%1, %2};" : "=l"(r) : "f"(lo), "f"(hi));
    return r;
}
__device__ __forceinline__ float lo2(u64 v) { return __uint_as_float((unsigned)v); }
__device__ __forceinline__ float hi2(u64 v) { return __uint_as_float((unsigned)(v >> 32)); }

__device__ __forceinline__ float sigmf_(float x) {
    return __fdividef(1.f, 1.f + __expf(-x));
}
__device__ __forceinline__ float tanhf_(float x) {
    float e = __expf(-2.f * fabsf(x));
    float r = __fdividef(1.f - e, 1.f + e);
    return copysignf(r, x);
}

// ---------------------------------------------------------------------------
// LSTM: one thread per pedestrian row, h/c in registers, 8 sequential steps.
// Hidden units processed in PAIRS (8 FFMA2 chains) to bound register pressure.
// ---------------------------------------------------------------------------
template<int D, bool ENC>
__global__ void __launch_bounds__(128, 2) lstm_kernel(
    const float* __restrict__ xseq,    // [T, N, D]
    const float* __restrict__ h0, const float* __restrict__ c0,   // [N,32]
    const float* __restrict__ Wih,     // [128, D]
    const float* __restrict__ Whh,     // [128, 32]
    const float* __restrict__ bih, const float* __restrict__ bhh, // [128]
    float* __restrict__ hsout,         // [T, N, 32]
    const float* __restrict__ traj_last, // [N,32] (ENC only)
    const float* __restrict__ znoise,    // [S,8]  (ENC only)
    float* __restrict__ enc)             // [N,72] (ENC only)
{
    __shared__ __align__(16) float sWhh[128 * 32];
    __shared__ __align__(16) float sWih[128 * D];
    __shared__ float sB[128];

    const int tid = threadIdx.x;
    for (int i = tid; i < 128 * 32; i += 128) sWhh[i] = Whh[i];
    for (int i = tid; i < 128 * D;  i += 128) sWih[i] = Wih[i];
    sB[tid] = bih[tid] + bhh[tid];
    __syncthreads();

    const int n = blockIdx.x * 128 + tid;

    float c[32];
    u64 h2[16];
    {
        const float4* hv4 = reinterpret_cast<const float4*>(h0 + (size_t)n * 32);
        const float4* cv4 = reinterpret_cast<const float4*>(c0 + (size_t)n * 32);
        #pragma unroll
        for (int j = 0; j < 8; j++) {
            float4 hv = hv4[j]; float4 cv = cv4[j];
            h2[2*j]   = pk2(hv.x, hv.y);
            h2[2*j+1] = pk2(hv.z, hv.w);
            c[4*j] = cv.x; c[4*j+1] = cv.y; c[4*j+2] = cv.z; c[4*j+3] = cv.w;
        }
    }

    #pragma unroll 1
    for (int t = 0; t < TT; t++) {
        float x0 = 0.f, x1 = 0.f, x2 = 0.f;
        u64 xv2[(D == 32) ? 16 : 1];
        if constexpr (D == 3) {
            const float* xp = xseq + ((size_t)t * NTOT + n) * 3;
            x0 = xp[0]; x1 = xp[1]; x2 = xp[2];
        } else {
            const float4* xp4 = reinterpret_cast<const float4*>(xseq + ((size_t)t * NTOT + n) * 32);
            #pragma unroll
            for (int j = 0; j < 8; j++) {
                float4 v = xp4[j];
                xv2[2*j]   = pk2(v.x, v.y);
                xv2[2*j+1] = pk2(v.z, v.w);
            }
        }

        float* op = hsout + ((size_t)t * NTOT + n) * 32;
        u64 h2n[16];

        #pragma unroll 1
        for (int kp = 0; kp < 16; kp++) {
            const int k0 = 2 * kp, k1 = 2 * kp + 1;
            const u64* wi0 = reinterpret_cast<const u64*>(sWhh + (k0      ) * 32);
            const u64* wf0 = reinterpret_cast<const u64*>(sWhh + (k0 + 32 ) * 32);
            const u64* wg0 = reinterpret_cast<const u64*>(sWhh + (k0 + 64 ) * 32);
            const u64* wo0 = reinterpret_cast<const u64*>(sWhh + (k0 + 96 ) * 32);
            const u64* wi1 = reinterpret_cast<const u64*>(sWhh + (k1      ) * 32);
            const u64* wf1 = reinterpret_cast<const u64*>(sWhh + (k1 + 32 ) * 32);
            const u64* wg1 = reinterpret_cast<const u64*>(sWhh + (k1 + 64 ) * 32);
            const u64* wo1 = reinterpret_cast<const u64*>(sWhh + (k1 + 96 ) * 32);
            u64 ai0 = 0, af0 = 0, ag0 = 0, ao0 = 0;
            u64 ai1 = 0, af1 = 0, ag1 = 0, ao1 = 0;
            #pragma unroll
            for (int j = 0; j < 16; j++) {
                u64 hv = h2[j];
                ai0 = ffma2(wi0[j], hv, ai0);
                af0 = ffma2(wf0[j], hv, af0);
                ag0 = ffma2(wg0[j], hv, ag0);
                ao0 = ffma2(wo0[j], hv, ao0);
                ai1 = ffma2(wi1[j], hv, ai1);
                af1 = ffma2(wf1[j], hv, af1);
                ag1 = ffma2(wg1[j], hv, ag1);
                ao1 = ffma2(wo1[j], hv, ao1);
            }
            if constexpr (D == 32) {
                const u64* vi0 = reinterpret_cast<const u64*>(sWih + (k0      ) * 32);
                const u64* vf0 = reinterpret_cast<const u64*>(sWih + (k0 + 32 ) * 32);
                const u64* vg0 = reinterpret_cast<const u64*>(sWih + (k0 + 64 ) * 32);
                const u64* vo0 = reinterpret_cast<const u64*>(sWih + (k0 + 96 ) * 32);
                const u64* vi1 = reinterpret_cast<const u64*>(sWih + (k1      ) * 32);
                const u64* vf1 = reinterpret_cast<const u64*>(sWih + (k1 + 32 ) * 32);
                const u64* vg1 = reinterpret_cast<const u64*>(sWih + (k1 + 64 ) * 32);
                const u64* vo1 = reinterpret_cast<const u64*>(sWih + (k1 + 96 ) * 32);
                #pragma unroll
                for (int j = 0; j < 16; j++) {
                    u64 xv = xv2[j];
                    ai0 = ffma2(vi0[j], xv, ai0);
                    af0 = ffma2(vf0[j], xv, af0);
                    ag0 = ffma2(vg0[j], xv, ag0);
                    ao0 = ffma2(vo0[j], xv, ao0);
                    ai1 = ffma2(vi1[j], xv, ai1);
                    af1 = ffma2(vf1[j], xv, af1);
                    ag1 = ffma2(vg1[j], xv, ag1);
                    ao1 = ffma2(vo1[j], xv, ao1);
                }
            }
            float gi0 = lo2(ai0) + hi2(ai0) + sB[k0];
            float gf0 = lo2(af0) + hi2(af0) + sB[32 + k0];
            float gg0 = lo2(ag0) + hi2(ag0) + sB[64 + k0];
            float go0 = lo2(ao0) + hi2(ao0) + sB[96 + k0];
            float gi1 = lo2(ai1) + hi2(ai1) + sB[k1];
            float gf1 = lo2(af1) + hi2(af1) + sB[32 + k1];
            float gg1 = lo2(ag1) + hi2(ag1) + sB[64 + k1];
            float go1 = lo2(ao1) + hi2(ao1) + sB[96 + k1];
            if constexpr (D == 3) {
                gi0 += sWih[(k0      )*3]*x0 + sWih[(k0      )*3+1]*x1 + sWih[(k0      )*3+2]*x2;
                gf0 += sWih[(k0 + 32 )*3]*x0 + sWih[(k0 + 32 )*3+1]*x1 + sWih[(k0 + 32 )*3+2]*x2;
                gg0 += sWih[(k0 + 64 )*3]*x0 + sWih[(k0 + 64 )*3+1]*x1 + sWih[(k0 + 64 )*3+2]*x2;
                go0 += sWih[(k0 + 96 )*3]*x0 + sWih[(k0 + 96 )*3+1]*x1 + sWih[(k0 + 96 )*3+2]*x2;
                gi1 += sWih[(k1      )*3]*x0 + sWih[(k1      )*3+1]*x1 + sWih[(k1      )*3+2]*x2;
                gf1 += sWih[(k1 + 32 )*3]*x0 + sWih[(k1 + 32 )*3+1]*x1 + sWih[(k1 + 32 )*3+2]*x2;
                gg1 += sWih[(k1 + 64 )*3]*x0 + sWih[(k1 + 64 )*3+1]*x1 + sWih[(k1 + 64 )*3+2]*x2;
                go1 += sWih[(k1 + 96 )*3]*x0 + sWih[(k1 + 96 )*3+1]*x1 + sWih[(k1 + 96 )*3+2]*x2;
            }
            float c0n = sigmf_(gf0) * c[k0] + sigmf_(gi0) * tanhf_(gg0);
            float c1n = sigmf_(gf1) * c[k1] + sigmf_(gi1) * tanhf_(gg1);
            c[k0] = c0n; c[k1] = c1n;
            float h0v = sigmf_(go0) * tanhf_(c0n);
            float h1v = sigmf_(go1) * tanhf_(c1n);
            h2n[kp] = pk2(h0v, h1v);
            *reinterpret_cast<float2*>(op + k0) = make_float2(h0v, h1v);
        }
        #pragma unroll
        for (int j = 0; j < 16; j++) h2[j] = h2n[j];

        if (ENC && t == TT - 1) {
            float* ep = enc + (size_t)n * 72;
            const float4* tl = reinterpret_cast<const float4*>(traj_last + (size_t)n * 32);
            #pragma unroll
            for (int j = 0; j < 8; j++) reinterpret_cast<float4*>(ep)[j] = tl[j];
            #pragma unroll
            for (int j = 0; j < 16; j++)
                reinterpret_cast<float2*>(ep + 32)[j] = make_float2(lo2(h2[j]), hi2(h2[j]));
            const float4* zp = reinterpret_cast<const float4*>(znoise + (size_t)(n >> 6) * 8);
            reinterpret_cast<float4*>(ep + 64)[0] = zp[0];
            reinterpret_cast<float4*>(ep + 64)[1] = zp[1];
        }
    }
}

// ---------------------------------------------------------------------------
// GAT encoder: one block per (scene, t). 256 threads. All tiles in shared.
// EM overlays the dead XN/W0S region -> 72.6 KB smem -> 3 blocks/SM.
// ---------------------------------------------------------------------------
#define GAT_SMEM_FLOATS 18160
#define GAT_SMEM_BYTES  (GAT_SMEM_FLOATS * 4)

__global__ void __launch_bounds__(256, 3) gat_kernel(
    const float* __restrict__ trajhs,   // [T, N, 32]
    const float* __restrict__ w0,       // [4,32,16]
    const float* __restrict__ asrc0, const float* __restrict__ adst0,  // [4,16]
    const float* __restrict__ bias0,    // [16]
    const float* __restrict__ w1,       // [1,64,32]
    const float* __restrict__ asrc1, const float* __restrict__ adst1,  // [32]
    const float* __restrict__ bias1,    // [32]
    float* __restrict__ gout)           // [T, N, 32]
{
    extern __shared__ __align__(16) float sm[];
    float* XN  = sm;           // 64 x 33           (dead after hp0)
    float* W0S = sm + 2112;    // 32 x 64           (dead after hp0)
    float* EM  = sm;           // 64 x 65 = 4160    (overlays XN+W0S, used after hp1)
    float* HP0 = sm + 4160;    // 64 x 68
    float* S0  = sm + 8512;    // 4 x 64
    float* D0  = sm + 8768;    // 4 x 64
    float* X1  = sm + 9024;    // 64 x 68
    float* W1S = sm + 13376;   // 64 x 32
    float* HP1 = sm + 15424;   // 64 x 36
    float* S1  = sm + 17728;   // 64
    float* D1  = sm + 17792;   // 64
    float* ES  = sm + 17856;   // 64
    float* A0S = sm + 17920;   // 64
    float* A0D = sm + 17984;   // 64
    float* A1S = sm + 18048;   // 32
    float* A1D = sm + 18080;   // 32
    float* B0  = sm + 18112;   // 16
    float* B1  = sm + 18128;   // 32

    const int tid = threadIdx.x;
    const int b = blockIdx.x;
    const int s = b >> 3, t = b & 7;

    const float* src = trajhs + ((size_t)t * NTOT + s * 64) * 32;
    for (int i = tid; i < 2048; i += 256) XN[(i >> 5) * 33 + (i & 31)] = src[i];
    for (int i = tid; i < 2048; i += 256) {
        int f = i >> 6, cc = i & 63;
        W0S[i] = w0[((cc >> 4) << 9) + (f << 4) + (cc & 15)];
    }
    for (int i = tid; i < 2048; i += 256) W1S[i] = w1[i];
    if (tid < 64)       { A0S[tid] = asrc0[tid]; A0D[tid] = adst0[tid]; }
    else if (tid < 96)  { A1S[tid - 64] = asrc1[tid - 64]; A1D[tid - 64] = adst1[tid - 64]; }
    else if (tid < 112) { B0[tid - 96] = bias0[tid - 96]; }
    else if (tid < 144) { B1[tid - 112] = bias1[tid - 112]; }
    __syncthreads();

    // --- instance norm over 64 peds, 32 features ---
    if (tid < 32) {
        const int f = tid;
        float m = 0.f;
        #pragma unroll 8
        for (int p = 0; p < 64; p++) m += XN[p * 33 + f];
        m *= 0.015625f;
        float v = 0.f;
        #pragma unroll 8
        for (int p = 0; p < 64; p++) { float d = XN[p * 33 + f] - m; v = fmaf(d, d, v); }
        float inv = rsqrtf(fmaf(v, 0.015625f, 1e-5f));
        #pragma unroll 8
        for (int p = 0; p < 64; p++) XN[p * 33 + f] = (XN[p * 33 + f] - m) * inv;
    }
    __syncthreads();

    // --- hp0 = xn @ w0 : [64x32] @ [32x64] ---
    {
        const int p  = tid >> 2;
        const int cb = (tid & 3) << 4;
        u64 acc[8] = {0, 0, 0, 0, 0, 0, 0, 0};
        #pragma unroll
        for (int f = 0; f < 32; f++) {
            float xv = XN[p * 33 + f];
            u64 xx = pk2(xv, xv);
            const u64* w = reinterpret_cast<const u64*>(W0S + f * 64 + cb);
            #pragma unroll
            for (int j = 0; j < 8; j++) acc[j] = ffma2(w[j], xx, acc[j]);
        }
        u64* dst = reinterpret_cast<u64*>(HP0 + p * 68 + cb);
        #pragma unroll
        for (int j = 0; j < 8; j++) dst[j] = acc[j];
    }
    __syncthreads();

    // --- s0, d0 ---
    {
        const int h = tid >> 6, p = tid & 63;
        const float* hb = HP0 + p * 68 + h * 16;
        const float* as = A0S + h * 16;
        const float* ad = A0D + h * 16;
        float sv = 0.f, dv = 0.f;
        #pragma unroll
        for (int o = 0; o < 16; o++) {
            float hv = hb[o];
            sv = fmaf(hv, as[o], sv);
            dv = fmaf(hv, ad[o], dv);
        }
        S0[h * 64 + p] = sv;
        D0[h * 64 + p] = dv;
    }
    __syncthreads();

    // --- attention0: softmax over q, apply to hp0, +bias, elu -> X1 ---
    {
        const int h = tid >> 6, p = tid & 63;
        const float sp = S0[h * 64 + p];
        const float* dd = D0 + h * 64;
        float mx = -3.4e38f;
        #pragma unroll 8
        for (int q = 0; q < 64; q++) {
            float e = sp + dd[q];
            e = e > 0.f ? e : 0.2f * e;
            mx = fmaxf(mx, e);
        }
        u64 acc[8] = {0, 0, 0, 0, 0, 0, 0, 0};
        float den = 0.f;
        #pragma unroll 2
        for (int q = 0; q < 64; q++) {
            float e = sp + dd[q];
            e = e > 0.f ? e : 0.2f * e;
            float w = __expf(e - mx);
            den += w;
            u64 ww = pk2(w, w);
            const u64* hq = reinterpret_cast<const u64*>(HP0 + q * 68 + h * 16);
            #pragma unroll
            for (int j = 0; j < 8; j++) acc[j] = ffma2(hq[j], ww, acc[j]);
        }
        float inv = __fdividef(1.f, den);
        float* xo = X1 + p * 68 + h * 16;
        #pragma unroll
        for (int j = 0; j < 8; j++) {
            float v0 = fmaf(lo2(acc[j]), inv, B0[2 * j]);
            float v1 = fmaf(hi2(acc[j]), inv, B0[2 * j + 1]);
            v0 = v0 > 0.f ? v0 : expm1f(v0);
            v1 = v1 > 0.f ? v1 : expm1f(v1);
            xo[2 * j] = v0;
            xo[2 * j + 1] = v1;
        }
    }
    __syncthreads();

    // --- instance norm over 64 peds, 64 features ---
    if (tid < 64) {
        const int f = tid;
        float m = 0.f;
        #pragma unroll 8
        for (int p = 0; p < 64; p++) m += X1[p * 68 + f];
        m *= 0.015625f;
        float v = 0.f;
        #pragma unroll 8
        for (int p = 0; p < 64; p++) { float d = X1[p * 68 + f] - m; v = fmaf(d, d, v); }
        float inv = rsqrtf(fmaf(v, 0.015625f, 1e-5f));
        #pragma unroll 8
        for (int p = 0; p < 64; p++) X1[p * 68 + f] = (X1[p * 68 + f] - m) * inv;
    }
    __syncthreads();

    // --- hp1 = x1 @ w1 : [64x64] @ [64x32] ---
    {
        const int p  = tid >> 2;
        const int ob = (tid & 3) << 3;
        u64 acc[4] = {0, 0, 0, 0};
        #pragma unroll
        for (int f = 0; f < 64; f++) {
            float xv = X1[p * 68 + f];
            u64 xx = pk2(xv, xv);
            const u64* w = reinterpret_cast<const u64*>(W1S + f * 32 + ob);
            #pragma unroll
            for (int j = 0; j < 4; j++) acc[j] = ffma2(w[j], xx, acc[j]);
        }
        u64* dst = reinterpret_cast<u64*>(HP1 + p * 36 + ob);
        #pragma unroll
        for (int j = 0; j < 4; j++) dst[j] = acc[j];
    }
    __syncthreads();

    // --- s1, d1 ---
    if (tid < 64) {
        const float* hb = HP1 + tid * 36;
        float sv = 0.f, dv = 0.f;
        #pragma unroll
        for (int o = 0; o < 32; o++) {
            float hv = hb[o];
            sv = fmaf(hv, A1S[o], sv);
            dv = fmaf(hv, A1D[o], dv);
        }
        S1[tid] = sv;
        D1[tid] = dv;
    }
    __syncthreads();

    // --- softmax weights for layer 1 (EM overlays dead XN/W0S) ---
    if (tid < 64) {
        const int p = tid;
        const float sp = S1[p];
        float mx = -3.4e38f;
        #pragma unroll 8
        for (int q = 0; q < 64; q++) {
            float e = sp + D1[q];
            e = e > 0.f ? e : 0.2f * e;
            mx = fmaxf(mx, e);
        }
        float den = 0.f;
        #pragma unroll 2
        for (int q = 0; q < 64; q++) {
            float e = sp + D1[q];
            e = e > 0.f ? e : 0.2f * e;
            float w = __expf(e - mx);
            EM[p * 65 + q] = w;
            den += w;
        }
        ES[p] = __fdividef(1.f, den);
    }
    __syncthreads();

    // --- apply attn1, +bias, write graph_in ---
    {
        const int p  = tid >> 2;
        const int ob = (tid & 3) << 3;
        u64 acc[4] = {0, 0, 0, 0};
        const float* ew = EM + p * 65;
        #pragma unroll 2
        for (int q = 0; q < 64; q++) {
            float w = ew[q];
            u64 ww = pk2(w, w);
            const u64* hq = reinterpret_cast<const u64*>(HP1 + q * 36 + ob);
            #pragma unroll
            for (int j = 0; j < 4; j++) acc[j] = ffma2(hq[j], ww, acc[j]);
        }
        float inv = ES[p];
        float2* gp = reinterpret_cast<float2*>(
            gout + ((size_t)t * NTOT + s * 64 + p) * 32 + ob);
        #pragma unroll
        for (int j = 0; j < 4; j++) {
            float v0 = fmaf(lo2(acc[j]), inv, B1[ob + 2 * j]);
            float v1 = fmaf(hi2(acc[j]), inv, B1[ob + 2 * j + 1]);
            gp[j] = make_float2(v0, v1);
        }
    }
}

// ---------------------------------------------------------------------------
extern "C" void kernel_launch(void* const* d_in, const int* in_sizes, int n_in,
                              void* d_out, int out_size)
{
    (void)in_sizes; (void)n_in; (void)out_size;
    const float* obs  = (const float*)d_in[0];
    const float* h0t  = (const float*)d_in[1];
    const float* c0t  = (const float*)d_in[2];
    const float* h0g  = (const float*)d_in[3];
    const float* c0g  = (const float*)d_in[4];
    const float* zn   = (const float*)d_in[5];
    const float* WihT = (const float*)d_in[6];
    const float* WhhT = (const float*)d_in[7];
    const float* bihT = (const float*)d_in[8];
    const float* bhhT = (const float*)d_in[9];
    const float* WihG = (const float*)d_in[10];
    const float* WhhG = (const float*)d_in[11];
    const float* bihG = (const float*)d_in[12];
    const float* bhhG = (const float*)d_in[13];
    const float* w0   = (const float*)d_in[14];
    const float* as0  = (const float*)d_in[15];
    const float* ad0  = (const float*)d_in[16];
    const float* b0   = (const float*)d_in[17];
    const float* w1   = (const float*)d_in[18];
    const float* as1  = (const float*)d_in[19];
    const float* ad1  = (const float*)d_in[20];
    const float* b1   = (const float*)d_in[21];

    float* out = (float*)d_out;
    float* enc = out;                                  // [N,72]
    float* ghs = out + (size_t)NTOT * 72;              // [T,N,32]
    float* ths = ghs + (size_t)TT * NTOT * 32;         // [T,N,32]

    float* gin = nullptr;
    cudaGetSymbolAddress((void**)&gin, g_graph_in);

    // 1) traj LSTM -> traj_hs (directly into output region)
    lstm_kernel<3, false><<<NTOT / 128, 128>>>(
        obs, h0t, c0t, WihT, WhhT, bihT, bhhT, ths, nullptr, nullptr, nullptr);

    // 2) GAT encoder -> graph_in scratch
    cudaFuncSetAttribute(gat_kernel,
                         cudaFuncAttributeMaxDynamicSharedMemorySize, GAT_SMEM_BYTES);
    gat_kernel<<<NS * TT, 256, GAT_SMEM_BYTES>>>(
        ths, w0, as0, ad0, b0, w1, as1, ad1, b1, gin);

    // 3) graph LSTM -> graph_hs + encoded (traj_hs[-1] | graph_hs[-1] | noise)
    lstm_kernel<32, true><<<NTOT / 128, 128>>>(
        gin, h0g, c0g, WihG, WhhG, bihG, bhhG, ghs,
        ths + (size_t)(TT - 1) * NTOT * 32, zn, enc);
}